// round 2
// baseline (speedup 1.0000x reference)
#include <cuda_runtime.h>

#define BATCH 1024
#define FEAT 256
#define NUM_CLASSES 100000
#define CLAMP_MIN 1e-12f
#define CLAMP_MAX 1e12f
#define WARPS_PER_BLOCK 8
#define ROWS_PER_BLOCK WARPS_PER_BLOCK

// Seed output with the masked-zero clamp constant: (C-1)*1e-12.
// Reference: loss = sum(d)/B + (C-1)*1e-12.
__global__ void init_out_kernel(float* out) {
    *out = (float)((double)(NUM_CLASSES - 1) * 1e-12);
}

__global__ __launch_bounds__(WARPS_PER_BLOCK * 32)
void center_loss_kernel(const float* __restrict__ x,
                        const float* __restrict__ centers,
                        const int* __restrict__ labels,   // JAX x64 disabled -> int32
                        float* __restrict__ out) {
    const int warp = threadIdx.x >> 5;
    const int lane = threadIdx.x & 31;
    const int row  = blockIdx.x * ROWS_PER_BLOCK + warp;

    int lbl = labels[row];
    // defensive clamp: never fault even if dtype/range assumption is wrong
    lbl = min(max(lbl, 0), NUM_CLASSES - 1);

    const float4* xr = reinterpret_cast<const float4*>(x + (size_t)row * FEAT);
    const float4* cr = reinterpret_cast<const float4*>(centers + (size_t)lbl * FEAT);

    // 256 floats = 64 float4 per row; 32 lanes * 2 float4 each.
    float p = 0.0f;
    #pragma unroll
    for (int i = 0; i < 2; i++) {
        float4 a = xr[lane + i * 32];
        float4 b = cr[lane + i * 32];
        float sx  = a.x * a.x + a.y * a.y + a.z * a.z + a.w * a.w;
        float sc  = b.x * b.x + b.y * b.y + b.z * b.z + b.w * b.w;
        float sxc = a.x * b.x + a.y * b.y + a.z * b.z + a.w * b.w;
        p += sx + sc - 2.0f * sxc;
    }

    // warp reduction
    #pragma unroll
    for (int off = 16; off > 0; off >>= 1)
        p += __shfl_xor_sync(0xFFFFFFFFu, p, off);

    __shared__ float bs[WARPS_PER_BLOCK];
    if (lane == 0) {
        bs[warp] = fminf(fmaxf(p, CLAMP_MIN), CLAMP_MAX);
    }
    __syncthreads();

    if (threadIdx.x == 0) {
        float s = 0.0f;
        #pragma unroll
        for (int w = 0; w < WARPS_PER_BLOCK; w++) s += bs[w];
        atomicAdd(out, s * (1.0f / BATCH));
    }
}

extern "C" void kernel_launch(void* const* d_in, const int* in_sizes, int n_in,
                              void* d_out, int out_size) {
    // Resolve inputs by element count, not position:
    //   x: 1024*256 = 262144, centers: 100000*256 = 25600000, labels: 1024
    const float* x = nullptr;
    const float* centers = nullptr;
    const int*   labels = nullptr;
    for (int i = 0; i < n_in; i++) {
        if (in_sizes[i] == BATCH * FEAT)            x       = (const float*)d_in[i];
        else if (in_sizes[i] == NUM_CLASSES * FEAT) centers = (const float*)d_in[i];
        else                                        labels  = (const int*)d_in[i];
    }
    float* out = (float*)d_out;

    init_out_kernel<<<1, 1>>>(out);
    center_loss_kernel<<<BATCH / ROWS_PER_BLOCK, WARPS_PER_BLOCK * 32>>>(
        x, centers, labels, out);
}